// round 13
// baseline (speedup 1.0000x reference)
#include <cuda_runtime.h>
#include <cuda_fp16.h>
#include <cstdint>
#include <math.h>

#define B_DIM 16
#define C_DIM 512
#define S_DIM 1024
#define NG    32
#define NH    8
#define HD    64

// ---------------- scratch (allocation-free __device__ globals) ----------------
__device__ __half g_h   [(size_t)B_DIM * S_DIM * C_DIM];
__device__ __half g_qkv [(size_t)B_DIM * S_DIM * 3 * C_DIM];
__device__ __half g_o   [(size_t)B_DIM * S_DIM * C_DIM];
__device__ __half g_wq  [3 * C_DIM * C_DIM];
__device__ __half g_wp  [C_DIM * C_DIM];
__device__ float  g_mean[B_DIM * NG];
__device__ float  g_inv [B_DIM * NG];

// ---------------- helpers ----------------
__device__ __forceinline__ uint32_t smem_u32(const void* p) {
    return (uint32_t)__cvta_generic_to_shared(p);
}
__device__ __forceinline__ void cp16(void* smem_dst, const void* gmem_src) {
    asm volatile("cp.async.ca.shared.global [%0], [%1], 16;"
                 :: "r"(smem_u32(smem_dst)), "l"(gmem_src));
}
__device__ __forceinline__ void cp_commit() {
    asm volatile("cp.async.commit_group;" ::: "memory");
}
template <int N>
__device__ __forceinline__ void cp_wait() {
    asm volatile("cp.async.wait_group %0;" :: "n"(N) : "memory");
}
__device__ __forceinline__ void ldm_x4(uint32_t& r0, uint32_t& r1, uint32_t& r2,
                                       uint32_t& r3, const void* p) {
    asm volatile("ldmatrix.sync.aligned.m8n8.x4.shared.b16 {%0,%1,%2,%3}, [%4];"
                 : "=r"(r0), "=r"(r1), "=r"(r2), "=r"(r3) : "r"(smem_u32(p)));
}
__device__ __forceinline__ void ldm_x4t(uint32_t& r0, uint32_t& r1, uint32_t& r2,
                                        uint32_t& r3, const void* p) {
    asm volatile("ldmatrix.sync.aligned.m8n8.x4.trans.shared.b16 {%0,%1,%2,%3}, [%4];"
                 : "=r"(r0), "=r"(r1), "=r"(r2), "=r"(r3) : "r"(smem_u32(p)));
}
__device__ __forceinline__ void ldm_x2(uint32_t& r0, uint32_t& r1, const void* p) {
    asm volatile("ldmatrix.sync.aligned.m8n8.x2.shared.b16 {%0,%1}, [%2];"
                 : "=r"(r0), "=r"(r1) : "r"(smem_u32(p)));
}
// fp32-accumulate mma
__device__ __forceinline__ void mma16816(float* c, const uint32_t* a, const uint32_t* b) {
    asm volatile(
        "mma.sync.aligned.m16n8k16.row.col.f32.f16.f16.f32 "
        "{%0,%1,%2,%3}, {%4,%5,%6,%7}, {%8,%9}, {%0,%1,%2,%3};"
        : "+f"(c[0]), "+f"(c[1]), "+f"(c[2]), "+f"(c[3])
        : "r"(a[0]), "r"(a[1]), "r"(a[2]), "r"(a[3]), "r"(b[0]), "r"(b[1]));
}
// fp16-accumulate mma
__device__ __forceinline__ void mma16816h(uint32_t* c, const uint32_t* a, const uint32_t* b) {
    asm volatile(
        "mma.sync.aligned.m16n8k16.row.col.f16.f16.f16.f16 "
        "{%0,%1}, {%2,%3,%4,%5}, {%6,%7}, {%0,%1};"
        : "+r"(c[0]), "+r"(c[1])
        : "r"(a[0]), "r"(a[1]), "r"(a[2]), "r"(a[3]), "r"(b[0]), "r"(b[1]));
}
__device__ __forceinline__ float ex2(float x) {
    float y;
    asm("ex2.approx.ftz.f32 %0, %1;" : "=f"(y) : "f"(x));
    return y;
}
__device__ __forceinline__ uint32_t h2_as_u32(__half2 h) {
    return *reinterpret_cast<uint32_t*>(&h);
}
__device__ __forceinline__ __half2 u32_as_h2(uint32_t u) {
    return *reinterpret_cast<__half2*>(&u);
}

// ---------------------------------------------------------------------------
// fp32 -> fp16 weight convert (single launch)
// ---------------------------------------------------------------------------
__global__ void convert_weights_kernel(const float* __restrict__ wq_f,
                                       const float* __restrict__ wp_f,
                                       __half* __restrict__ wq,
                                       __half* __restrict__ wp) {
    const int NQ = 3 * C_DIM * C_DIM;
    const int NP = C_DIM * C_DIM;
    int i = blockIdx.x * blockDim.x + threadIdx.x;
    if (i < NQ) wq[i] = __float2half(wq_f[i]);
    else if (i < NQ + NP) wp[i - NQ] = __float2half(wp_f[i - NQ]);
}

// ---------------------------------------------------------------------------
// GroupNorm pass 1
// ---------------------------------------------------------------------------
__global__ void gn_stats_kernel(const float* __restrict__ x,
                                float* __restrict__ meanArr,
                                float* __restrict__ invArr) {
    const int bg = blockIdx.x;
    const int NEL = (C_DIM / NG) * S_DIM;
    const float* xp = x + (size_t)bg * NEL;
    float sum = 0.f, sq = 0.f;
    for (int i = threadIdx.x; i < NEL; i += 256) {
        float v = xp[i];
        sum += v; sq += v * v;
    }
    __shared__ float ssum[256], ssq[256];
    ssum[threadIdx.x] = sum; ssq[threadIdx.x] = sq;
    __syncthreads();
    for (int s = 128; s > 0; s >>= 1) {
        if (threadIdx.x < s) {
            ssum[threadIdx.x] += ssum[threadIdx.x + s];
            ssq[threadIdx.x]  += ssq[threadIdx.x + s];
        }
        __syncthreads();
    }
    if (threadIdx.x == 0) {
        float mean = ssum[0] * (1.f / NEL);
        float var  = ssq[0] * (1.f / NEL) - mean * mean;
        meanArr[bg] = mean;
        invArr[bg]  = rsqrtf(var + 1e-5f);
    }
}

// ---------------------------------------------------------------------------
// GroupNorm pass 2 + transpose -> h[b,s,c] fp16
// ---------------------------------------------------------------------------
__global__ void gn_transpose_kernel(const float* __restrict__ x,
                                    const float* __restrict__ gamma,
                                    const float* __restrict__ beta,
                                    const float* __restrict__ meanArr,
                                    const float* __restrict__ invArr,
                                    __half* __restrict__ h) {
    __shared__ float t[64][33];
    const int b = blockIdx.z, c0 = blockIdx.y * 64, s0 = blockIdx.x * 32;
    const int tx = threadIdx.x, ty = threadIdx.y;
#pragma unroll
    for (int i = 0; i < 8; i++) {
        int cr = ty + i * 8;
        int c = c0 + cr;
        float v = x[((size_t)b * C_DIM + c) * S_DIM + s0 + tx];
        int g = c >> 4;
        float mean = meanArr[b * NG + g], inv = invArr[b * NG + g];
        t[cr][tx] = (v - mean) * inv * gamma[c] + beta[c];
    }
    __syncthreads();
#pragma unroll
    for (int i = 0; i < 4; i++) {
        int s = s0 + ty + i * 8;
        __half2 val = __floats2half2_rn(t[tx * 2][ty + i * 8],
                                        t[tx * 2 + 1][ty + i * 8]);
        *(__half2*)&h[((size_t)b * S_DIM + s) * C_DIM + c0 + tx * 2] = val;
    }
}

// ---------------------------------------------------------------------------
// Fused flash attention v4: t-tile 64, 3-stage K/V pipeline, ONE sync/iter.
// ---------------------------------------------------------------------------
#define SMK 72
#define FLASH_SMEM ((128 + 6 * 64) * SMK * 2)   // Q + 3-stage K(64) + 3-stage V(64)

__global__ __launch_bounds__(256, 2)
void flash_kernel(const __half* __restrict__ qkv, __half* __restrict__ o) {
    extern __shared__ __half sm[];
    __half (*Qs)[SMK] = reinterpret_cast<__half(*)[SMK]>(sm);
    __half (*Ks)[SMK] = reinterpret_cast<__half(*)[SMK]>(sm + 128 * SMK);        // [3][64]
    __half (*Vs)[SMK] = reinterpret_cast<__half(*)[SMK]>(sm + (128 + 192) * SMK);// [3][64]

    const int tid = threadIdx.x, lane = tid & 31, w = tid >> 5;
    const int bh = blockIdx.y, b = bh >> 3, hh = bh & 7;
    const int s0 = blockIdx.x * 128;

    const __half* qbase = qkv + (size_t)b * (S_DIM * 3 * C_DIM) + hh * 64;
    const __half* kbase = qbase + 512;
    const __half* vbase = qbase + 1024;

    const int qrow = tid >> 1, qcol = (tid & 1) * 32;
    const int krow = tid >> 2, kcol = (tid & 3) * 16;

    auto load_kv = [&](int st, int it) {
        const __half* kp = kbase + (size_t)(it * 64 + krow) * 1536 + kcol;
        const __half* vp = vbase + (size_t)(it * 64 + krow) * 1536 + kcol;
#pragma unroll
        for (int c = 0; c < 2; c++) {
            cp16(&Ks[st * 64 + krow][kcol + c * 8], kp + c * 8);
            cp16(&Vs[st * 64 + krow][kcol + c * 8], vp + c * 8);
        }
        cp_commit();
    };

    // Q (group), then stages 0 and 1
#pragma unroll
    for (int c = 0; c < 4; c++)
        cp16(&Qs[qrow][qcol + c * 8],
             qbase + (size_t)(s0 + qrow) * 1536 + qcol + c * 8);
    cp_commit();
    load_kv(0, 0);
    load_kv(1, 1);

    cp_wait<2>();        // Q complete
    __syncthreads();

    uint32_t qf[4][4];
#pragma unroll
    for (int kj = 0; kj < 4; kj++)
        ldm_x4(qf[kj][0], qf[kj][1], qf[kj][2], qf[kj][3],
               &Qs[w * 16 + (lane & 15)][kj * 16 + ((lane >> 4) << 3)]);

    const float C2 = 0.125f * 1.44269504f;
    float m0 = -1e30f, m1 = -1e30f, l0 = 0.f, l1 = 0.f;
    float ao[8][4];
#pragma unroll
    for (int i = 0; i < 8; i++)
#pragma unroll
        for (int j = 0; j < 4; j++) ao[i][j] = 0.f;

    for (int it = 0; it < 16; it++) {
        if (it + 1 < 16) cp_wait<1>();
        else             cp_wait<0>();
        __syncthreads();                 // single barrier per iteration
        const int st = it % 3;

        // prefetch stage it+2 (overwrites stage (it-1)%3 — safe after the sync)
        if (it + 2 < 16) load_kv((it + 2) % 3, it + 2);

        // ---- S = Q K^T (f16 accumulate) ----
        uint32_t ash[8][2];
#pragma unroll
        for (int i = 0; i < 8; i++) { ash[i][0] = 0u; ash[i][1] = 0u; }

#pragma unroll
        for (int kj = 0; kj < 4; kj++) {
            uint32_t bf[4][4];
#pragma unroll
            for (int j = 0; j < 4; j++)
                ldm_x4(bf[j][0], bf[j][1], bf[j][2], bf[j][3],
                       &Ks[st * 64 + j * 16 + (lane & 15)]
                          [kj * 16 + ((lane >> 4) << 3)]);
#pragma unroll
            for (int j = 0; j < 4; j++) {
                uint32_t bA[2] = {bf[j][0], bf[j][2]};
                uint32_t bB[2] = {bf[j][1], bf[j][3]};
                mma16816h(ash[2 * j],     qf[kj], bA);
                mma16816h(ash[2 * j + 1], qf[kj], bB);
            }
        }

        float as[8][4];
#pragma unroll
        for (int nt = 0; nt < 8; nt++) {
            float2 lo = __half22float2(u32_as_h2(ash[nt][0]));
            float2 hi = __half22float2(u32_as_h2(ash[nt][1]));
            as[nt][0] = lo.x; as[nt][1] = lo.y;
            as[nt][2] = hi.x; as[nt][3] = hi.y;
        }

        // ---- online softmax ----
        float mx0 = -1e30f, mx1 = -1e30f;
#pragma unroll
        for (int nt = 0; nt < 8; nt++) {
            mx0 = fmaxf(mx0, fmaxf(as[nt][0], as[nt][1]));
            mx1 = fmaxf(mx1, fmaxf(as[nt][2], as[nt][3]));
        }
        mx0 = fmaxf(mx0, __shfl_xor_sync(0xffffffffu, mx0, 1));
        mx0 = fmaxf(mx0, __shfl_xor_sync(0xffffffffu, mx0, 2));
        mx1 = fmaxf(mx1, __shfl_xor_sync(0xffffffffu, mx1, 1));
        mx1 = fmaxf(mx1, __shfl_xor_sync(0xffffffffu, mx1, 2));
        const float mn0 = fmaxf(m0, mx0), mn1 = fmaxf(m1, mx1);
        const float cr0 = ex2((m0 - mn0) * C2), cr1 = ex2((m1 - mn1) * C2);
        m0 = mn0; m1 = mn1;
        l0 *= cr0; l1 *= cr1;
#pragma unroll
        for (int tn = 0; tn < 8; tn++) {
            ao[tn][0] *= cr0; ao[tn][1] *= cr0;
            ao[tn][2] *= cr1; ao[tn][3] *= cr1;
        }

        uint32_t ph[4][4];
        float sum0 = 0.f, sum1 = 0.f;
#pragma unroll
        for (int nt = 0; nt < 8; nt++) {
            float p0 = ex2((as[nt][0] - mn0) * C2);
            float p1 = ex2((as[nt][1] - mn0) * C2);
            float p2 = ex2((as[nt][2] - mn1) * C2);
            float p3 = ex2((as[nt][3] - mn1) * C2);
            sum0 += p0 + p1; sum1 += p2 + p3;
            const int kj = nt >> 1, hi = (nt & 1) * 2;
            ph[kj][hi]     = h2_as_u32(__floats2half2_rn(p0, p1));
            ph[kj][hi + 1] = h2_as_u32(__floats2half2_rn(p2, p3));
        }
        sum0 += __shfl_xor_sync(0xffffffffu, sum0, 1);
        sum0 += __shfl_xor_sync(0xffffffffu, sum0, 2);
        sum1 += __shfl_xor_sync(0xffffffffu, sum1, 1);
        sum1 += __shfl_xor_sync(0xffffffffu, sum1, 2);
        l0 += sum0; l1 += sum1;

        // ---- O += P V (fp32 accumulate) ----
#pragma unroll
        for (int kj = 0; kj < 4; kj++) {
            uint32_t vf[4][4];
#pragma unroll
            for (int dj = 0; dj < 4; dj++)
                ldm_x4t(vf[dj][0], vf[dj][1], vf[dj][2], vf[dj][3],
                        &Vs[st * 64 + kj * 16 + (lane & 15)]
                           [dj * 16 + ((lane >> 4) << 3)]);
#pragma unroll
            for (int dj = 0; dj < 4; dj++) {
                uint32_t bA[2] = {vf[dj][0], vf[dj][1]};
                uint32_t bB[2] = {vf[dj][2], vf[dj][3]};
                mma16816(ao[2 * dj],     ph[kj], bA);
                mma16816(ao[2 * dj + 1], ph[kj], bB);
            }
        }
    }

    const float r0 = 1.f / l0, r1 = 1.f / l1;
    const int srow = s0 + w * 16 + (lane >> 2);
    __half* op = o + ((size_t)b * S_DIM + srow) * C_DIM + hh * 64 + (lane & 3) * 2;
#pragma unroll
    for (int tn = 0; tn < 8; tn++) {
        *(__half2*)(op + tn * 8) =
            __floats2half2_rn(ao[tn][0] * r0, ao[tn][1] * r0);
        *(__half2*)(op + 8 * C_DIM + tn * 8) =
            __floats2half2_rn(ao[tn][2] * r1, ao[tn][3] * r1);
    }
}

// ---------------------------------------------------------------------------
// HGEMM-wide (QKV): BM=128, BN=256, BK=32, 8 warps (2m x 4n), warp 64x64,
// f16 accumulate, 3-stage cp.async, ONE sync per iteration.
// ---------------------------------------------------------------------------
#define WG_SK 40
#define WG_STAGES 3
#define WG_SMEM (WG_STAGES * (128 + 256) * WG_SK * 2)   // 92160 B

__global__ __launch_bounds__(256, 2)
void hgemm_wide_kernel(const __half* __restrict__ A, const __half* __restrict__ B,
                       __half* __restrict__ C, const float* __restrict__ bias,
                       int K, int lda, int ldb, int ldc,
                       long sA, long sC) {
    extern __shared__ __half wsm[];
    __half (*As)[128][WG_SK] = reinterpret_cast<__half(*)[128][WG_SK]>(wsm);
    __half (*Bs)[256][WG_SK] =
        reinterpret_cast<__half(*)[256][WG_SK]>(wsm + WG_STAGES * 128 * WG_SK);

    const int tid = threadIdx.x;
    const int lane = tid & 31, wid = tid >> 5;
    const int wm = wid >> 2, wn = wid & 3;

    A += blockIdx.z * sA;
    const size_t cbase = (size_t)blockIdx.z * sC;
    const int m0 = blockIdx.y * 128;
    const int n0 = blockIdx.x * 256;

    const int lr = tid >> 2;
    const int lc = (tid & 3) * 8;

    uint32_t acc[4][8][2];
#pragma unroll
    for (int i = 0; i < 4; i++)
#pragma unroll
        for (int j = 0; j < 8; j++) { acc[i][j][0] = 0u; acc[i][j][1] = 0u; }

    const int nit = K >> 5;

    auto load_stage = [&](int st, int it) {
        const int k0 = it << 5;
#pragma unroll
        for (int p = 0; p < 2; p++) {
            int r = lr + p * 64;
            cp16(&As[st][r][lc], A + (size_t)(m0 + r) * lda + k0 + lc);
        }
#pragma unroll
        for (int p = 0; p < 4; p++) {
            int r = lr + p * 64;
            cp16(&Bs[st][r][lc], B + (size_t)(n0 + r) * ldb + k0 + lc);
        }
        cp_commit();
    };

    load_stage(0, 0);
    load_stage(1, 1);

    const int arow = wm * 64 + (lane & 15);
    const int brow = wn * 64 + (lane & 15);
    const int col8 = (lane >> 4) << 3;

    for (int it = 0; it < nit; it++) {
        if (it + 1 < nit) cp_wait<1>();
        else              cp_wait<0>();
        __syncthreads();                 // single barrier per iteration
        const int st = it % 3;

        if (it + 2 < nit) load_stage((it + 2) % 3, it + 2);

#pragma unroll
        for (int ks = 0; ks < 2; ks++) {
            const int kb = ks * 16;
            uint32_t a[4][4], bf[4][4];
#pragma unroll
            for (int bt = 0; bt < 4; bt++)
                ldm_x4(bf[bt][0], bf[bt][1], bf[bt][2], bf[bt][3],
                       &Bs[st][brow + bt * 16][kb + col8]);
#pragma unroll
            for (int tm = 0; tm < 4; tm++)
                ldm_x4(a[tm][0], a[tm][1], a[tm][2], a[tm][3],
                       &As[st][arow + tm * 16][kb + col8]);
#pragma unroll
            for (int tm = 0; tm < 4; tm++)
#pragma unroll
                for (int bt = 0; bt < 4; bt++) {
                    uint32_t bA[2] = {bf[bt][0], bf[bt][2]};
                    uint32_t bB[2] = {bf[bt][1], bf[bt][3]};
                    mma16816h(acc[tm][2 * bt],     a[tm], bA);
                    mma16816h(acc[tm][2 * bt + 1], a[tm], bB);
                }
        }
    }

#pragma unroll
    for (int tm = 0; tm < 4; tm++) {
        const int row = m0 + wm * 64 + tm * 16 + (lane >> 2);
#pragma unroll
        for (int tn = 0; tn < 8; tn++) {
            const int col = n0 + wn * 64 + tn * 8 + (lane & 3) * 2;
            float2 lo = __half22float2(u32_as_h2(acc[tm][tn][0]));
            float2 hi = __half22float2(u32_as_h2(acc[tm][tn][1]));
            float b0 = bias[col], b1 = bias[col + 1];
            const size_t a0 = cbase + (size_t)row * ldc + col;
            const size_t a1 = cbase + (size_t)(row + 8) * ldc + col;
            *(__half2*)(C + a0) = __floats2half2_rn(lo.x + b0, lo.y + b1);
            *(__half2*)(C + a1) = __floats2half2_rn(hi.x + b0, hi.y + b1);
        }
    }
}

// ---------------------------------------------------------------------------
// HGEMM v6 (proj): 128 threads, BM=64, BN=128, BK=32, f32 accumulate.
// ---------------------------------------------------------------------------
template <int BIAS_MODE, bool RESID, typename OutT>
__global__ __launch_bounds__(128, 4)
void hgemm_kernel(const __half* __restrict__ A, const __half* __restrict__ B,
                  OutT* __restrict__ C, const float* __restrict__ bias,
                  const float* __restrict__ resid,
                  int K, int lda, int ldb, int ldc, int nInner,
                  long sAo, long sAi, long sBo, long sBi,
                  long sCo, long sCi, float alpha) {
    constexpr int BM = 64, BN = 128, BK = 32;
    constexpr int SK = BK + 8;

    __shared__ __half As[2][BM][SK];
    __shared__ __half Bs[2][BN][SK];

    const int tid = threadIdx.x;
    const int lane = tid & 31, wn = tid >> 5;

    const int z = blockIdx.z;
    const int zo = z / nInner, zi = z - zo * nInner;
    A += zo * sAo + zi * sAi;
    B += zo * sBo + zi * sBi;
    const size_t cbase = (size_t)(zo * sCo + zi * sCi);
    const int m0 = blockIdx.y * BM;
    const int n0 = blockIdx.x * BN;

    const int lrow = tid >> 2;
    const int lcol = (tid & 3) * 8;

    float acc[4][4][4];
#pragma unroll
    for (int i = 0; i < 4; i++)
#pragma unroll
        for (int j = 0; j < 4; j++)
#pragma unroll
            for (int q = 0; q < 4; q++) acc[i][j][q] = 0.f;

    const int nit = K >> 5;

    auto load_stage = [&](int st, int it) {
        const int k0 = it << 5;
#pragma unroll
        for (int p = 0; p < 2; p++) {
            int r = lrow + p * 32;
            cp16(&As[st][r][lcol], A + (size_t)(m0 + r) * lda + k0 + lcol);
        }
#pragma unroll
        for (int p = 0; p < 4; p++) {
            int r = lrow + p * 32;
            cp16(&Bs[st][r][lcol], B + (size_t)(n0 + r) * ldb + k0 + lcol);
        }
        cp_commit();
    };

    load_stage(0, 0);

    const int arow = lane & 15;
    const int acol8 = (lane >> 4) << 3;
    const int brow = wn * 32 + (lane & 7);
    const int bcol8 = ((lane >> 3) & 1) * 8;

    for (int it = 0; it < nit; it++) {
        if (it + 1 < nit) {
            load_stage((it + 1) & 1, it + 1);
            cp_wait<1>();
        } else {
            cp_wait<0>();
        }
        __syncthreads();
        const int st = it & 1;

        uint32_t a[4][4], b0[4][2], b1[4][2];
#pragma unroll
        for (int tn = 0; tn < 4; tn++)
            ldm_x2(b0[tn][0], b0[tn][1], &Bs[st][brow + tn * 8][bcol8]);
#pragma unroll
        for (int tn = 0; tn < 4; tn++)
            ldm_x2(b1[tn][0], b1[tn][1], &Bs[st][brow + tn * 8][16 + bcol8]);
#pragma unroll
        for (int tm = 0; tm < 4; tm++)
            ldm_x4(a[tm][0], a[tm][1], a[tm][2], a[tm][3],
                   &As[st][arow + tm * 16][acol8]);
#pragma unroll
        for (int tm = 0; tm < 4; tm++)
#pragma unroll
            for (int tn = 0; tn < 4; tn++)
                mma16816(acc[tm][tn], a[tm], b0[tn]);
#pragma unroll
        for (int tm = 0; tm < 4; tm++)
            ldm_x4(a[tm][0], a[tm][1], a[tm][2], a[tm][3],
                   &As[st][arow + tm * 16][16 + acol8]);
#pragma unroll
        for (int tm = 0; tm < 4; tm++)
#pragma unroll
            for (int tn = 0; tn < 4; tn++)
                mma16816(acc[tm][tn], a[tm], b1[tn]);
        __syncthreads();
    }

#pragma unroll
    for (int tm = 0; tm < 4; tm++) {
        const int row = m0 + tm * 16 + (lane >> 2);
#pragma unroll
        for (int tn = 0; tn < 4; tn++) {
            const int col = n0 + wn * 32 + tn * 8 + (lane & 3) * 2;
            float v0 = acc[tm][tn][0] * alpha, v1 = acc[tm][tn][1] * alpha;
            float v2 = acc[tm][tn][2] * alpha, v3 = acc[tm][tn][3] * alpha;
            if (BIAS_MODE == 1) {
                v0 += bias[row]; v1 += bias[row];
                v2 += bias[row + 8]; v3 += bias[row + 8];
            }
            if (BIAS_MODE == 2) {
                v0 += bias[col]; v2 += bias[col];
                v1 += bias[col + 1]; v3 += bias[col + 1];
            }
            const size_t a0 = cbase + (size_t)row * ldc + col;
            const size_t a1 = cbase + (size_t)(row + 8) * ldc + col;
            if (sizeof(OutT) == 4) {
                float2 q0 = make_float2(v0, v1), q1 = make_float2(v2, v3);
                if (RESID) {
                    float2 x0 = *(const float2*)(resid + a0);
                    float2 x1 = *(const float2*)(resid + a1);
                    q0.x += x0.x; q0.y += x0.y; q1.x += x1.x; q1.y += x1.y;
                }
                *(float2*)((float*)C + a0) = q0;
                *(float2*)((float*)C + a1) = q1;
            } else {
                *(__half2*)((__half*)C + a0) = __floats2half2_rn(v0, v1);
                *(__half2*)((__half*)C + a1) = __floats2half2_rn(v2, v3);
            }
        }
    }
}

// ---------------------------------------------------------------------------
// Launch
// ---------------------------------------------------------------------------
extern "C" void kernel_launch(void* const* d_in, const int* in_sizes, int n_in,
                              void* d_out, int out_size) {
    const float* x      = (const float*)d_in[0];
    const float* norm_w = (const float*)d_in[1];
    const float* norm_b = (const float*)d_in[2];
    const float* qkv_w  = (const float*)d_in[3];
    const float* qkv_b  = (const float*)d_in[4];
    const float* proj_w = (const float*)d_in[5];
    const float* proj_b = (const float*)d_in[6];
    float* out = (float*)d_out;

    __half *h, *qkv, *obuf, *wq, *wp;
    float *meanA, *invA;
    cudaGetSymbolAddress((void**)&h,     g_h);
    cudaGetSymbolAddress((void**)&qkv,   g_qkv);
    cudaGetSymbolAddress((void**)&obuf,  g_o);
    cudaGetSymbolAddress((void**)&wq,    g_wq);
    cudaGetSymbolAddress((void**)&wp,    g_wp);
    cudaGetSymbolAddress((void**)&meanA, g_mean);
    cudaGetSymbolAddress((void**)&invA,  g_inv);

    const long SC  = (long)S_DIM * C_DIM;
    const long S3C = (long)S_DIM * 3 * C_DIM;

    // 0. fp16 weight copies
    convert_weights_kernel<<<(4 * C_DIM * C_DIM + 255) / 256, 256>>>(
        qkv_w, proj_w, wq, wp);

    // 1. GroupNorm -> h[b,s,c] fp16
    gn_stats_kernel<<<B_DIM * NG, 256>>>(x, meanA, invA);
    gn_transpose_kernel<<<dim3(32, 8, 16), dim3(32, 8)>>>(x, norm_w, norm_b,
                                                          meanA, invA, h);

    // 2. QKV (wide tile, f16 acc, 3-stage): M=s(1024), N=o(1536), K=512.
    cudaFuncSetAttribute(hgemm_wide_kernel,
                         cudaFuncAttributeMaxDynamicSharedMemorySize, WG_SMEM);
    hgemm_wide_kernel<<<dim3(6, 8, 16), 256, WG_SMEM>>>(
        h, wq, qkv, qkv_b,
        512, 512, 512, 1536,
        SC, S3C);

    // 3. Fused flash attention (3-stage) -> obuf[b,s,c] fp16
    cudaFuncSetAttribute(flash_kernel,
                         cudaFuncAttributeMaxDynamicSharedMemorySize, FLASH_SMEM);
    flash_kernel<<<dim3(S_DIM / 128, B_DIM * NH), 256, FLASH_SMEM>>>(qkv, obuf);

    // 4. Proj (f32 accumulate): M=co(512), N=s, K=512. bias per m, resid=x.
    hgemm_kernel<1, true, float><<<dim3(8, 8, 16), 128>>>(
        wp, obuf, out, proj_b, x,
        512, 512, 512, 1024,
        1, 0, 0, SC, 0, SC, 0, 1.0f);
}

// round 15
// speedup vs baseline: 1.0321x; 1.0321x over previous
#include <cuda_runtime.h>
#include <cuda_fp16.h>
#include <cstdint>
#include <math.h>

#define B_DIM 16
#define C_DIM 512
#define S_DIM 1024
#define NG    32
#define NH    8
#define HD    64

// ---------------- scratch (allocation-free __device__ globals) ----------------
__device__ __half g_h   [(size_t)B_DIM * S_DIM * C_DIM];
__device__ __half g_qkv [(size_t)B_DIM * S_DIM * 3 * C_DIM];
__device__ __half g_o   [(size_t)B_DIM * S_DIM * C_DIM];
__device__ __half g_wq  [3 * C_DIM * C_DIM];
__device__ __half g_wp  [C_DIM * C_DIM];
__device__ float  g_mean[B_DIM * NG];
__device__ float  g_inv [B_DIM * NG];

// ---------------- helpers ----------------
__device__ __forceinline__ uint32_t smem_u32(const void* p) {
    return (uint32_t)__cvta_generic_to_shared(p);
}
__device__ __forceinline__ void cp16(void* smem_dst, const void* gmem_src) {
    asm volatile("cp.async.ca.shared.global [%0], [%1], 16;"
                 :: "r"(smem_u32(smem_dst)), "l"(gmem_src));
}
__device__ __forceinline__ void cp_commit() {
    asm volatile("cp.async.commit_group;" ::: "memory");
}
template <int N>
__device__ __forceinline__ void cp_wait() {
    asm volatile("cp.async.wait_group %0;" :: "n"(N) : "memory");
}
__device__ __forceinline__ void ldm_x4(uint32_t& r0, uint32_t& r1, uint32_t& r2,
                                       uint32_t& r3, const void* p) {
    asm volatile("ldmatrix.sync.aligned.m8n8.x4.shared.b16 {%0,%1,%2,%3}, [%4];"
                 : "=r"(r0), "=r"(r1), "=r"(r2), "=r"(r3) : "r"(smem_u32(p)));
}
__device__ __forceinline__ void ldm_x4t(uint32_t& r0, uint32_t& r1, uint32_t& r2,
                                        uint32_t& r3, const void* p) {
    asm volatile("ldmatrix.sync.aligned.m8n8.x4.trans.shared.b16 {%0,%1,%2,%3}, [%4];"
                 : "=r"(r0), "=r"(r1), "=r"(r2), "=r"(r3) : "r"(smem_u32(p)));
}
__device__ __forceinline__ void ldm_x2(uint32_t& r0, uint32_t& r1, const void* p) {
    asm volatile("ldmatrix.sync.aligned.m8n8.x2.shared.b16 {%0,%1}, [%2];"
                 : "=r"(r0), "=r"(r1) : "r"(smem_u32(p)));
}
__device__ __forceinline__ void mma16816(float* c, const uint32_t* a, const uint32_t* b) {
    asm volatile(
        "mma.sync.aligned.m16n8k16.row.col.f32.f16.f16.f32 "
        "{%0,%1,%2,%3}, {%4,%5,%6,%7}, {%8,%9}, {%0,%1,%2,%3};"
        : "+f"(c[0]), "+f"(c[1]), "+f"(c[2]), "+f"(c[3])
        : "r"(a[0]), "r"(a[1]), "r"(a[2]), "r"(a[3]), "r"(b[0]), "r"(b[1]));
}
__device__ __forceinline__ void mma16816h(uint32_t* c, const uint32_t* a, const uint32_t* b) {
    asm volatile(
        "mma.sync.aligned.m16n8k16.row.col.f16.f16.f16.f16 "
        "{%0,%1}, {%2,%3,%4,%5}, {%6,%7}, {%0,%1};"
        : "+r"(c[0]), "+r"(c[1])
        : "r"(a[0]), "r"(a[1]), "r"(a[2]), "r"(a[3]), "r"(b[0]), "r"(b[1]));
}
__device__ __forceinline__ float ex2(float x) {
    float y;
    asm("ex2.approx.ftz.f32 %0, %1;" : "=f"(y) : "f"(x));
    return y;
}
__device__ __forceinline__ uint32_t h2_as_u32(__half2 h) {
    return *reinterpret_cast<uint32_t*>(&h);
}
__device__ __forceinline__ __half2 u32_as_h2(uint32_t u) {
    return *reinterpret_cast<__half2*>(&u);
}

// ---------------------------------------------------------------------------
// fp32 -> fp16 weight convert, float4-vectorized (4 elems/thread)
// ---------------------------------------------------------------------------
__global__ void convert_weights_kernel(const float* __restrict__ wq_f,
                                       const float* __restrict__ wp_f,
                                       __half* __restrict__ wq,
                                       __half* __restrict__ wp) {
    const int NQ4 = (3 * C_DIM * C_DIM) / 4;
    const int NP4 = (C_DIM * C_DIM) / 4;
    int i = blockIdx.x * blockDim.x + threadIdx.x;
    if (i < NQ4) {
        float4 v = ((const float4*)wq_f)[i];
        __half2* d = (__half2*)(wq + i * 4);
        d[0] = __floats2half2_rn(v.x, v.y);
        d[1] = __floats2half2_rn(v.z, v.w);
    } else if (i < NQ4 + NP4) {
        int j = i - NQ4;
        float4 v = ((const float4*)wp_f)[j];
        __half2* d = (__half2*)(wp + j * 4);
        d[0] = __floats2half2_rn(v.x, v.y);
        d[1] = __floats2half2_rn(v.z, v.w);
    }
}

// ---------------------------------------------------------------------------
// GroupNorm pass 1 (float4 loads)
// ---------------------------------------------------------------------------
__global__ void gn_stats_kernel(const float* __restrict__ x,
                                float* __restrict__ meanArr,
                                float* __restrict__ invArr) {
    const int bg = blockIdx.x;
    const int NEL = (C_DIM / NG) * S_DIM;     // 16384
    const float4* xp = (const float4*)(x + (size_t)bg * NEL);
    float sum = 0.f, sq = 0.f;
#pragma unroll 4
    for (int i = threadIdx.x; i < NEL / 4; i += 256) {
        float4 v = xp[i];
        sum += (v.x + v.y) + (v.z + v.w);
        sq  += (v.x * v.x + v.y * v.y) + (v.z * v.z + v.w * v.w);
    }
    __shared__ float ssum[256], ssq[256];
    ssum[threadIdx.x] = sum; ssq[threadIdx.x] = sq;
    __syncthreads();
    for (int s = 128; s > 0; s >>= 1) {
        if (threadIdx.x < s) {
            ssum[threadIdx.x] += ssum[threadIdx.x + s];
            ssq[threadIdx.x]  += ssq[threadIdx.x + s];
        }
        __syncthreads();
    }
    if (threadIdx.x == 0) {
        float mean = ssum[0] * (1.f / NEL);
        float var  = ssq[0] * (1.f / NEL) - mean * mean;
        meanArr[bg] = mean;
        invArr[bg]  = rsqrtf(var + 1e-5f);
    }
}

// ---------------------------------------------------------------------------
// GroupNorm pass 2 + transpose -> h[b,s,c] fp16
// ---------------------------------------------------------------------------
__global__ void gn_transpose_kernel(const float* __restrict__ x,
                                    const float* __restrict__ gamma,
                                    const float* __restrict__ beta,
                                    const float* __restrict__ meanArr,
                                    const float* __restrict__ invArr,
                                    __half* __restrict__ h) {
    __shared__ float t[64][33];
    const int b = blockIdx.z, c0 = blockIdx.y * 64, s0 = blockIdx.x * 32;
    const int tx = threadIdx.x, ty = threadIdx.y;
#pragma unroll
    for (int i = 0; i < 8; i++) {
        int cr = ty + i * 8;
        int c = c0 + cr;
        float v = x[((size_t)b * C_DIM + c) * S_DIM + s0 + tx];
        int g = c >> 4;
        float mean = meanArr[b * NG + g], inv = invArr[b * NG + g];
        t[cr][tx] = (v - mean) * inv * gamma[c] + beta[c];
    }
    __syncthreads();
#pragma unroll
    for (int i = 0; i < 4; i++) {
        int s = s0 + ty + i * 8;
        __half2 val = __floats2half2_rn(t[tx * 2][ty + i * 8],
                                        t[tx * 2 + 1][ty + i * 8]);
        *(__half2*)&h[((size_t)b * S_DIM + s) * C_DIM + c0 + tx * 2] = val;
    }
}

// ---------------------------------------------------------------------------
// Fused flash attention (R12 config: t-tile 64, 2-stage, f16-acc QK^T)
// ---------------------------------------------------------------------------
#define SMK 72
#define FLASH_SMEM ((128 + 4 * 64) * SMK * 2)

__global__ __launch_bounds__(256, 2)
void flash_kernel(const __half* __restrict__ qkv, __half* __restrict__ o) {
    extern __shared__ __half sm[];
    __half (*Qs)[SMK] = reinterpret_cast<__half(*)[SMK]>(sm);
    __half (*Ks)[SMK] = reinterpret_cast<__half(*)[SMK]>(sm + 128 * SMK);
    __half (*Vs)[SMK] = reinterpret_cast<__half(*)[SMK]>(sm + 256 * SMK);

    const int tid = threadIdx.x, lane = tid & 31, w = tid >> 5;
    const int bh = blockIdx.y, b = bh >> 3, hh = bh & 7;
    const int s0 = blockIdx.x * 128;

    const __half* qbase = qkv + (size_t)b * (S_DIM * 3 * C_DIM) + hh * 64;
    const __half* kbase = qbase + 512;
    const __half* vbase = qbase + 1024;

    const int qrow = tid >> 1, qcol = (tid & 1) * 32;
    const int krow = tid >> 2, kcol = (tid & 3) * 16;

#pragma unroll
    for (int c = 0; c < 4; c++)
        cp16(&Qs[qrow][qcol + c * 8],
             qbase + (size_t)(s0 + qrow) * 1536 + qcol + c * 8);
    cp_commit();
    {
        const __half* kp = kbase + (size_t)krow * 1536 + kcol;
        const __half* vp = vbase + (size_t)krow * 1536 + kcol;
#pragma unroll
        for (int c = 0; c < 2; c++) {
            cp16(&Ks[krow][kcol + c * 8], kp + c * 8);
            cp16(&Vs[krow][kcol + c * 8], vp + c * 8);
        }
    }
    cp_commit();
    cp_wait<1>();
    __syncthreads();

    uint32_t qf[4][4];
#pragma unroll
    for (int kj = 0; kj < 4; kj++)
        ldm_x4(qf[kj][0], qf[kj][1], qf[kj][2], qf[kj][3],
               &Qs[w * 16 + (lane & 15)][kj * 16 + ((lane >> 4) << 3)]);

    const float C2 = 0.125f * 1.44269504f;
    float m0 = -1e30f, m1 = -1e30f, l0 = 0.f, l1 = 0.f;
    float ao[8][4];
#pragma unroll
    for (int i = 0; i < 8; i++)
#pragma unroll
        for (int j = 0; j < 4; j++) ao[i][j] = 0.f;

    for (int it = 0; it < 16; it++) {
        if (it < 15) {
            const int stn = (it + 1) & 1;
            const __half* kp = kbase + (size_t)((it + 1) * 64 + krow) * 1536 + kcol;
            const __half* vp = vbase + (size_t)((it + 1) * 64 + krow) * 1536 + kcol;
#pragma unroll
            for (int c = 0; c < 2; c++) {
                cp16(&Ks[stn * 64 + krow][kcol + c * 8], kp + c * 8);
                cp16(&Vs[stn * 64 + krow][kcol + c * 8], vp + c * 8);
            }
            cp_commit();
            cp_wait<1>();
        } else {
            cp_wait<0>();
        }
        __syncthreads();
        const int st = it & 1;

        // ---- S = Q K^T (f16 accumulate) ----
        uint32_t ash[8][2];
#pragma unroll
        for (int i = 0; i < 8; i++) { ash[i][0] = 0u; ash[i][1] = 0u; }

#pragma unroll
        for (int kj = 0; kj < 4; kj++) {
            uint32_t bf[4][4];
#pragma unroll
            for (int j = 0; j < 4; j++)
                ldm_x4(bf[j][0], bf[j][1], bf[j][2], bf[j][3],
                       &Ks[st * 64 + j * 16 + (lane & 15)]
                          [kj * 16 + ((lane >> 4) << 3)]);
#pragma unroll
            for (int j = 0; j < 4; j++) {
                uint32_t bA[2] = {bf[j][0], bf[j][2]};
                uint32_t bB[2] = {bf[j][1], bf[j][3]};
                mma16816h(ash[2 * j],     qf[kj], bA);
                mma16816h(ash[2 * j + 1], qf[kj], bB);
            }
        }

        float as[8][4];
#pragma unroll
        for (int nt = 0; nt < 8; nt++) {
            float2 lo = __half22float2(u32_as_h2(ash[nt][0]));
            float2 hi = __half22float2(u32_as_h2(ash[nt][1]));
            as[nt][0] = lo.x; as[nt][1] = lo.y;
            as[nt][2] = hi.x; as[nt][3] = hi.y;
        }

        // ---- online softmax ----
        float mx0 = -1e30f, mx1 = -1e30f;
#pragma unroll
        for (int nt = 0; nt < 8; nt++) {
            mx0 = fmaxf(mx0, fmaxf(as[nt][0], as[nt][1]));
            mx1 = fmaxf(mx1, fmaxf(as[nt][2], as[nt][3]));
        }
        mx0 = fmaxf(mx0, __shfl_xor_sync(0xffffffffu, mx0, 1));
        mx0 = fmaxf(mx0, __shfl_xor_sync(0xffffffffu, mx0, 2));
        mx1 = fmaxf(mx1, __shfl_xor_sync(0xffffffffu, mx1, 1));
        mx1 = fmaxf(mx1, __shfl_xor_sync(0xffffffffu, mx1, 2));
        const float mn0 = fmaxf(m0, mx0), mn1 = fmaxf(m1, mx1);
        const float cr0 = ex2((m0 - mn0) * C2), cr1 = ex2((m1 - mn1) * C2);
        m0 = mn0; m1 = mn1;
        l0 *= cr0; l1 *= cr1;
#pragma unroll
        for (int tn = 0; tn < 8; tn++) {
            ao[tn][0] *= cr0; ao[tn][1] *= cr0;
            ao[tn][2] *= cr1; ao[tn][3] *= cr1;
        }

        uint32_t ph[4][4];
        float sum0 = 0.f, sum1 = 0.f;
#pragma unroll
        for (int nt = 0; nt < 8; nt++) {
            float p0 = ex2((as[nt][0] - mn0) * C2);
            float p1 = ex2((as[nt][1] - mn0) * C2);
            float p2 = ex2((as[nt][2] - mn1) * C2);
            float p3 = ex2((as[nt][3] - mn1) * C2);
            sum0 += p0 + p1; sum1 += p2 + p3;
            const int kj = nt >> 1, hi = (nt & 1) * 2;
            ph[kj][hi]     = h2_as_u32(__floats2half2_rn(p0, p1));
            ph[kj][hi + 1] = h2_as_u32(__floats2half2_rn(p2, p3));
        }
        sum0 += __shfl_xor_sync(0xffffffffu, sum0, 1);
        sum0 += __shfl_xor_sync(0xffffffffu, sum0, 2);
        sum1 += __shfl_xor_sync(0xffffffffu, sum1, 1);
        sum1 += __shfl_xor_sync(0xffffffffu, sum1, 2);
        l0 += sum0; l1 += sum1;

        // ---- O += P V (fp32 accumulate) ----
#pragma unroll
        for (int kj = 0; kj < 4; kj++) {
            uint32_t vf[4][4];
#pragma unroll
            for (int dj = 0; dj < 4; dj++)
                ldm_x4t(vf[dj][0], vf[dj][1], vf[dj][2], vf[dj][3],
                        &Vs[st * 64 + kj * 16 + (lane & 15)]
                           [dj * 16 + ((lane >> 4) << 3)]);
#pragma unroll
            for (int dj = 0; dj < 4; dj++) {
                uint32_t bA[2] = {vf[dj][0], vf[dj][1]};
                uint32_t bB[2] = {vf[dj][2], vf[dj][3]};
                mma16816(ao[2 * dj],     ph[kj], bA);
                mma16816(ao[2 * dj + 1], ph[kj], bB);
            }
        }
        __syncthreads();
    }

    const float r0 = 1.f / l0, r1 = 1.f / l1;
    const int srow = s0 + w * 16 + (lane >> 2);
    __half* op = o + ((size_t)b * S_DIM + srow) * C_DIM + hh * 64 + (lane & 3) * 2;
#pragma unroll
    for (int tn = 0; tn < 8; tn++) {
        *(__half2*)(op + tn * 8) =
            __floats2half2_rn(ao[tn][0] * r0, ao[tn][1] * r0);
        *(__half2*)(op + 8 * C_DIM + tn * 8) =
            __floats2half2_rn(ao[tn][2] * r1, ao[tn][3] * r1);
    }
}

// ---------------------------------------------------------------------------
// HGEMM-wide (QKV): R12 config. BM=128, BN=256, BK=32, warp 64x64, f16 acc,
// 2-stage cp.async.
// ---------------------------------------------------------------------------
#define WG_SK 40
#define WG_SMEM (2 * (128 + 256) * WG_SK * 2)

__global__ __launch_bounds__(256, 2)
void hgemm_wide_kernel(const __half* __restrict__ A, const __half* __restrict__ B,
                       __half* __restrict__ C, const float* __restrict__ bias,
                       int K, int lda, int ldb, int ldc,
                       long sA, long sC) {
    extern __shared__ __half wsm[];
    __half (*As)[128][WG_SK] = reinterpret_cast<__half(*)[128][WG_SK]>(wsm);
    __half (*Bs)[256][WG_SK] =
        reinterpret_cast<__half(*)[256][WG_SK]>(wsm + 2 * 128 * WG_SK);

    const int tid = threadIdx.x;
    const int lane = tid & 31, wid = tid >> 5;
    const int wm = wid >> 2, wn = wid & 3;

    A += blockIdx.z * sA;
    const size_t cbase = (size_t)blockIdx.z * sC;
    const int m0 = blockIdx.y * 128;
    const int n0 = blockIdx.x * 256;

    const int lr = tid >> 2;
    const int lc = (tid & 3) * 8;

    uint32_t acc[4][8][2];
#pragma unroll
    for (int i = 0; i < 4; i++)
#pragma unroll
        for (int j = 0; j < 8; j++) { acc[i][j][0] = 0u; acc[i][j][1] = 0u; }

    const int nit = K >> 5;

    auto load_stage = [&](int st, int it) {
        const int k0 = it << 5;
#pragma unroll
        for (int p = 0; p < 2; p++) {
            int r = lr + p * 64;
            cp16(&As[st][r][lc], A + (size_t)(m0 + r) * lda + k0 + lc);
        }
#pragma unroll
        for (int p = 0; p < 4; p++) {
            int r = lr + p * 64;
            cp16(&Bs[st][r][lc], B + (size_t)(n0 + r) * ldb + k0 + lc);
        }
        cp_commit();
    };

    load_stage(0, 0);

    const int arow = wm * 64 + (lane & 15);
    const int brow = wn * 64 + (lane & 15);
    const int col8 = (lane >> 4) << 3;

    for (int it = 0; it < nit; it++) {
        if (it + 1 < nit) {
            load_stage((it + 1) & 1, it + 1);
            cp_wait<1>();
        } else {
            cp_wait<0>();
        }
        __syncthreads();
        const int st = it & 1;

#pragma unroll
        for (int ks = 0; ks < 2; ks++) {
            const int kb = ks * 16;
            uint32_t a[4][4], bf[4][4];
#pragma unroll
            for (int bt = 0; bt < 4; bt++)
                ldm_x4(bf[bt][0], bf[bt][1], bf[bt][2], bf[bt][3],
                       &Bs[st][brow + bt * 16][kb + col8]);
#pragma unroll
            for (int tm = 0; tm < 4; tm++)
                ldm_x4(a[tm][0], a[tm][1], a[tm][2], a[tm][3],
                       &As[st][arow + tm * 16][kb + col8]);
#pragma unroll
            for (int tm = 0; tm < 4; tm++)
#pragma unroll
                for (int bt = 0; bt < 4; bt++) {
                    uint32_t bA[2] = {bf[bt][0], bf[bt][2]};
                    uint32_t bB[2] = {bf[bt][1], bf[bt][3]};
                    mma16816h(acc[tm][2 * bt],     a[tm], bA);
                    mma16816h(acc[tm][2 * bt + 1], a[tm], bB);
                }
        }
        __syncthreads();
    }

#pragma unroll
    for (int tm = 0; tm < 4; tm++) {
        const int row = m0 + wm * 64 + tm * 16 + (lane >> 2);
#pragma unroll
        for (int tn = 0; tn < 8; tn++) {
            const int col = n0 + wn * 64 + tn * 8 + (lane & 3) * 2;
            float2 lo = __half22float2(u32_as_h2(acc[tm][tn][0]));
            float2 hi = __half22float2(u32_as_h2(acc[tm][tn][1]));
            float b0 = bias[col], b1 = bias[col + 1];
            const size_t a0 = cbase + (size_t)row * ldc + col;
            const size_t a1 = cbase + (size_t)(row + 8) * ldc + col;
            *(__half2*)(C + a0) = __floats2half2_rn(lo.x + b0, lo.y + b1);
            *(__half2*)(C + a1) = __floats2half2_rn(hi.x + b0, hi.y + b1);
        }
    }
}

// ---------------------------------------------------------------------------
// HGEMM v6 (proj): 128 threads, BM=64, BN=128, BK=32, f32 accumulate.
// ---------------------------------------------------------------------------
template <int BIAS_MODE, bool RESID, typename OutT>
__global__ __launch_bounds__(128, 4)
void hgemm_kernel(const __half* __restrict__ A, const __half* __restrict__ B,
                  OutT* __restrict__ C, const float* __restrict__ bias,
                  const float* __restrict__ resid,
                  int K, int lda, int ldb, int ldc, int nInner,
                  long sAo, long sAi, long sBo, long sBi,
                  long sCo, long sCi, float alpha) {
    constexpr int BM = 64, BN = 128, BK = 32;
    constexpr int SK = BK + 8;

    __shared__ __half As[2][BM][SK];
    __shared__ __half Bs[2][BN][SK];

    const int tid = threadIdx.x;
    const int lane = tid & 31, wn = tid >> 5;

    const int z = blockIdx.z;
    const int zo = z / nInner, zi = z - zo * nInner;
    A += zo * sAo + zi * sAi;
    B += zo * sBo + zi * sBi;
    const size_t cbase = (size_t)(zo * sCo + zi * sCi);
    const int m0 = blockIdx.y * BM;
    const int n0 = blockIdx.x * BN;

    const int lrow = tid >> 2;
    const int lcol = (tid & 3) * 8;

    float acc[4][4][4];
#pragma unroll
    for (int i = 0; i < 4; i++)
#pragma unroll
        for (int j = 0; j < 4; j++)
#pragma unroll
            for (int q = 0; q < 4; q++) acc[i][j][q] = 0.f;

    const int nit = K >> 5;

    auto load_stage = [&](int st, int it) {
        const int k0 = it << 5;
#pragma unroll
        for (int p = 0; p < 2; p++) {
            int r = lrow + p * 32;
            cp16(&As[st][r][lcol], A + (size_t)(m0 + r) * lda + k0 + lcol);
        }
#pragma unroll
        for (int p = 0; p < 4; p++) {
            int r = lrow + p * 32;
            cp16(&Bs[st][r][lcol], B + (size_t)(n0 + r) * ldb + k0 + lcol);
        }
        cp_commit();
    };

    load_stage(0, 0);

    const int arow = lane & 15;
    const int acol8 = (lane >> 4) << 3;
    const int brow = wn * 32 + (lane & 7);
    const int bcol8 = ((lane >> 3) & 1) * 8;

    for (int it = 0; it < nit; it++) {
        if (it + 1 < nit) {
            load_stage((it + 1) & 1, it + 1);
            cp_wait<1>();
        } else {
            cp_wait<0>();
        }
        __syncthreads();
        const int st = it & 1;

        uint32_t a[4][4], b0[4][2], b1[4][2];
#pragma unroll
        for (int tn = 0; tn < 4; tn++)
            ldm_x2(b0[tn][0], b0[tn][1], &Bs[st][brow + tn * 8][bcol8]);
#pragma unroll
        for (int tn = 0; tn < 4; tn++)
            ldm_x2(b1[tn][0], b1[tn][1], &Bs[st][brow + tn * 8][16 + bcol8]);
#pragma unroll
        for (int tm = 0; tm < 4; tm++)
            ldm_x4(a[tm][0], a[tm][1], a[tm][2], a[tm][3],
                   &As[st][arow + tm * 16][acol8]);
#pragma unroll
        for (int tm = 0; tm < 4; tm++)
#pragma unroll
            for (int tn = 0; tn < 4; tn++)
                mma16816(acc[tm][tn], a[tm], b0[tn]);
#pragma unroll
        for (int tm = 0; tm < 4; tm++)
            ldm_x4(a[tm][0], a[tm][1], a[tm][2], a[tm][3],
                   &As[st][arow + tm * 16][16 + acol8]);
#pragma unroll
        for (int tm = 0; tm < 4; tm++)
#pragma unroll
            for (int tn = 0; tn < 4; tn++)
                mma16816(acc[tm][tn], a[tm], b1[tn]);
        __syncthreads();
    }

#pragma unroll
    for (int tm = 0; tm < 4; tm++) {
        const int row = m0 + tm * 16 + (lane >> 2);
#pragma unroll
        for (int tn = 0; tn < 4; tn++) {
            const int col = n0 + wn * 32 + tn * 8 + (lane & 3) * 2;
            float v0 = acc[tm][tn][0] * alpha, v1 = acc[tm][tn][1] * alpha;
            float v2 = acc[tm][tn][2] * alpha, v3 = acc[tm][tn][3] * alpha;
            if (BIAS_MODE == 1) {
                v0 += bias[row]; v1 += bias[row];
                v2 += bias[row + 8]; v3 += bias[row + 8];
            }
            if (BIAS_MODE == 2) {
                v0 += bias[col]; v2 += bias[col];
                v1 += bias[col + 1]; v3 += bias[col + 1];
            }
            const size_t a0 = cbase + (size_t)row * ldc + col;
            const size_t a1 = cbase + (size_t)(row + 8) * ldc + col;
            if (sizeof(OutT) == 4) {
                float2 q0 = make_float2(v0, v1), q1 = make_float2(v2, v3);
                if (RESID) {
                    float2 x0 = *(const float2*)(resid + a0);
                    float2 x1 = *(const float2*)(resid + a1);
                    q0.x += x0.x; q0.y += x0.y; q1.x += x1.x; q1.y += x1.y;
                }
                *(float2*)((float*)C + a0) = q0;
                *(float2*)((float*)C + a1) = q1;
            } else {
                *(__half2*)((__half*)C + a0) = __floats2half2_rn(v0, v1);
                *(__half2*)((__half*)C + a1) = __floats2half2_rn(v2, v3);
            }
        }
    }
}

// ---------------------------------------------------------------------------
// Launch (single stream — overlap measured unprofitable in R14)
// ---------------------------------------------------------------------------
extern "C" void kernel_launch(void* const* d_in, const int* in_sizes, int n_in,
                              void* d_out, int out_size) {
    const float* x      = (const float*)d_in[0];
    const float* norm_w = (const float*)d_in[1];
    const float* norm_b = (const float*)d_in[2];
    const float* qkv_w  = (const float*)d_in[3];
    const float* qkv_b  = (const float*)d_in[4];
    const float* proj_w = (const float*)d_in[5];
    const float* proj_b = (const float*)d_in[6];
    float* out = (float*)d_out;

    __half *h, *qkv, *obuf, *wq, *wp;
    float *meanA, *invA;
    cudaGetSymbolAddress((void**)&h,     g_h);
    cudaGetSymbolAddress((void**)&qkv,   g_qkv);
    cudaGetSymbolAddress((void**)&obuf,  g_o);
    cudaGetSymbolAddress((void**)&wq,    g_wq);
    cudaGetSymbolAddress((void**)&wp,    g_wp);
    cudaGetSymbolAddress((void**)&meanA, g_mean);
    cudaGetSymbolAddress((void**)&invA,  g_inv);

    const long SC  = (long)S_DIM * C_DIM;
    const long S3C = (long)S_DIM * 3 * C_DIM;

    // 0. fp16 weight copies (float4-vectorized)
    convert_weights_kernel<<<(C_DIM * C_DIM + 255) / 256, 256>>>(
        qkv_w, proj_w, wq, wp);

    // 1. GroupNorm -> h[b,s,c] fp16
    gn_stats_kernel<<<B_DIM * NG, 256>>>(x, meanA, invA);
    gn_transpose_kernel<<<dim3(32, 8, 16), dim3(32, 8)>>>(x, norm_w, norm_b,
                                                          meanA, invA, h);

    // 2. QKV (wide tile, f16 acc): M=s(1024), N=o(1536), K=512.
    cudaFuncSetAttribute(hgemm_wide_kernel,
                         cudaFuncAttributeMaxDynamicSharedMemorySize, WG_SMEM);
    hgemm_wide_kernel<<<dim3(6, 8, 16), 256, WG_SMEM>>>(
        h, wq, qkv, qkv_b,
        512, 512, 512, 1536,
        SC, S3C);

    // 3. Fused flash attention -> obuf[b,s,c] fp16
    cudaFuncSetAttribute(flash_kernel,
                         cudaFuncAttributeMaxDynamicSharedMemorySize, FLASH_SMEM);
    flash_kernel<<<dim3(S_DIM / 128, B_DIM * NH), 256, FLASH_SMEM>>>(qkv, obuf);

    // 4. Proj (f32 accumulate): M=co(512), N=s, K=512. bias per m, resid=x.
    hgemm_kernel<1, true, float><<<dim3(8, 8, 16), 128>>>(
        wp, obuf, out, proj_b, x,
        512, 512, 512, 1024,
        1, 0, 0, SC, 0, SC, 0, 1.0f);
}